// round 16
// baseline (speedup 1.0000x reference)
#include <cuda_runtime.h>
#include <cuda_fp16.h>
#include <math.h>
#include <stdint.h>

#define B_BATCH 4096
#define H_DIM   1024
#define IN_DIM  10338
#define IN_PAD  10368
#define OUT_DIM 229
#define OUT_PAD 256
#define BN_EPS  1e-5f
#define WSCALE    512.0f
#define INV_WSCALE (1.0f / 512.0f)

// ---------------- MMA GEMM tiling -------------------------------------------
#define BM 128
#define BNT 64
#define BK 64
#define SMS 72                              // smem row stride in fp16 (144B)
#define A_CB (BM * SMS * 2)                 // 18432 bytes per class
#define B_CB (BNT * SMS * 2)                // 9216 bytes per class
#define OFF_AH 0
#define OFF_AL (A_CB)
#define OFF_BH (2 * A_CB)
#define OFF_BL (2 * A_CB + B_CB)
#define STAGE_BYTES (2 * A_CB + 2 * B_CB)   // 55296
#define NSTAGE 3
#define SMEM_REQ (NSTAGE * STAGE_BYTES)     // 165888

#define BN_CH 16                            // bn stats row chunks

// ---------------- scratch (device globals; no allocation allowed) ----------
__device__ float g_A [(size_t)B_BATCH * H_DIM];   // split-K partial z=0
__device__ float g_A2[(size_t)B_BATCH * H_DIM];   // split-K partial z=1
__device__ float g_H0[(size_t)B_BATCH * H_DIM];
__device__ float g_H1[(size_t)B_BATCH * H_DIM];
__device__ float g_O4[(size_t)B_BATCH * OUT_DIM];
__device__ float g_scale[H_DIM];
__device__ float g_shift[H_DIM];
__device__ float g_psum[BN_CH * H_DIM];
__device__ float g_psq [BN_CH * H_DIM];

__device__ __half g_Xh[(size_t)B_BATCH * IN_PAD];
__device__ __half g_Xl[(size_t)B_BATCH * IN_PAD];
__device__ __half g_Ah[(size_t)B_BATCH * H_DIM];
__device__ __half g_Al[(size_t)B_BATCH * H_DIM];

__device__ __half g_W1h[(size_t)H_DIM * IN_PAD];
__device__ __half g_W1l[(size_t)H_DIM * IN_PAD];
__device__ __half g_W2ah[(size_t)H_DIM * H_DIM];
__device__ __half g_W2al[(size_t)H_DIM * H_DIM];
__device__ __half g_W2bh[(size_t)H_DIM * H_DIM];
__device__ __half g_W2bl[(size_t)H_DIM * H_DIM];
__device__ __half g_W3ah[(size_t)H_DIM * H_DIM];
__device__ __half g_W3al[(size_t)H_DIM * H_DIM];
__device__ __half g_W3bh[(size_t)H_DIM * H_DIM];
__device__ __half g_W3bl[(size_t)H_DIM * H_DIM];
__device__ __half g_W4h[(size_t)OUT_PAD * H_DIM];
__device__ __half g_W4l[(size_t)OUT_PAD * H_DIM];

// ---------------- PTX helpers (baseline PTX; no sm_103a features) ----------
__device__ __forceinline__ uint32_t smem_u32(const void* p) {
    uint32_t a;
    asm("{ .reg .u64 t; cvta.to.shared.u64 t, %1; cvt.u32.u64 %0, t; }"
        : "=r"(a) : "l"(p));
    return a;
}
__device__ __forceinline__ void cp16(uint32_t dst, const void* src) {
    asm volatile("cp.async.cg.shared.global [%0], [%1], 16;" :: "r"(dst), "l"(src));
}
__device__ __forceinline__ void cp_commit() { asm volatile("cp.async.commit_group;" ::: "memory"); }
__device__ __forceinline__ void cp_wait2()  { asm volatile("cp.async.wait_group 2;" ::: "memory"); }
__device__ __forceinline__ void cp_wait1()  { asm volatile("cp.async.wait_group 1;" ::: "memory"); }
__device__ __forceinline__ void cp_wait0()  { asm volatile("cp.async.wait_group 0;" ::: "memory"); }

__device__ __forceinline__ void ldsm4(uint32_t r[4], uint32_t addr) {
    asm volatile("ldmatrix.sync.aligned.m8n8.x4.shared.b16 {%0,%1,%2,%3}, [%4];"
                 : "=r"(r[0]), "=r"(r[1]), "=r"(r[2]), "=r"(r[3]) : "r"(addr));
}
__device__ __forceinline__ void mma_f16(float c[4], const uint32_t a[4],
                                        const uint32_t b[2]) {
    asm volatile(
        "mma.sync.aligned.m16n8k16.row.col.f32.f16.f16.f32 "
        "{%0,%1,%2,%3}, {%4,%5,%6,%7}, {%8,%9}, {%0,%1,%2,%3};"
        : "+f"(c[0]), "+f"(c[1]), "+f"(c[2]), "+f"(c[3])
        : "r"(a[0]), "r"(a[1]), "r"(a[2]), "r"(a[3]), "r"(b[0]), "r"(b[1]));
}

// 2-way fp16 split: v = h + l + e, |e| <= 2^-23 |v| (for normal-range l)
__device__ __forceinline__ void split2(float v, __half& h, __half& l) {
    h = __float2half_rn(v);
    l = __float2half_rn(v - __half2float(h));
}

// ---------------- GEMM (fp16 2-split, 3-term, dual acc + fp32 master) ------
// Split-K along blockIdx.z: z-slice covers K chunks [z*nst, (z+1)*nst).
// Partial output z goes to C + z*M*Nact; bias added only by z==0.
__global__ void __launch_bounds__(256, 1)
mma_gemm(const __half* __restrict__ Ah, const __half* __restrict__ Al,
         const __half* __restrict__ Bh, const __half* __restrict__ Bl,
         const float* __restrict__ bias, float* __restrict__ C,
         int Kpad, int Nact, int nst, float outScale)
{
    extern __shared__ char smem[];
    const int tid  = threadIdx.x;
    const int wid  = tid >> 5;
    const int lane = tid & 31;
    const int m0   = blockIdx.y * BM;
    const int n0   = blockIdx.x * BNT;
    const int zb   = blockIdx.z * nst;
    const uint32_t sb = smem_u32(smem);

    const int wm = wid & 3;
    const int wn = wid >> 2;

    float acc_hi[2][4][4], acc_lo[2][4][4], master[2][4][4];
#pragma unroll
    for (int i = 0; i < 2; i++)
#pragma unroll
        for (int j = 0; j < 4; j++)
#pragma unroll
            for (int k = 0; k < 4; k++) {
                acc_hi[i][j][k] = 0.f; acc_lo[i][j][k] = 0.f; master[i][j][k] = 0.f;
            }

    const int a_row  = lane & 15;
    const int a_koff = (lane >> 4) << 3;
    const int b_nr   = (lane & 7) + ((lane >> 4) << 3);
    const int b_koff = ((lane >> 3) & 1) << 3;

    const uint32_t a_rb0 = (uint32_t)(wm * 32 + a_row) * (SMS * 2) + a_koff * 2;
    const uint32_t a_rb1 = a_rb0 + 16 * (SMS * 2);
    const uint32_t b_rb0 = (uint32_t)(wn * 32 + b_nr) * (SMS * 2) + b_koff * 2;
    const uint32_t b_rb1 = b_rb0 + 16 * (SMS * 2);

    auto load_stage = [&](int s, int chunk) {
        uint32_t st = sb + s * STAGE_BYTES;
        int k0 = chunk * BK;
#pragma unroll
        for (int i = 0; i < 4; i++) {                 // A: 128 rows x 8 granules
            int g = tid + i * 256;
            int row = g >> 3, gc = g & 7;
            size_t  go = (size_t)(m0 + row) * Kpad + k0 + gc * 8;
            uint32_t so = row * (SMS * 2) + gc * 16;
            cp16(st + OFF_AH + so, Ah + go);
            cp16(st + OFF_AL + so, Al + go);
        }
#pragma unroll
        for (int i = 0; i < 2; i++) {                 // B: 64 rows x 8 granules
            int g = tid + i * 256;
            int row = g >> 3, gc = g & 7;
            size_t  go = (size_t)(n0 + row) * Kpad + k0 + gc * 8;
            uint32_t so = row * (SMS * 2) + gc * 16;
            cp16(st + OFF_BH + so, Bh + go);
            cp16(st + OFF_BL + so, Bl + go);
        }
    };

    // prologue: fill 3 stages
#pragma unroll
    for (int i = 0; i < NSTAGE; i++) {
        if (i < nst) load_stage(i, zb + i);
        cp_commit();
    }

    int buf = 0;
    for (int s = 0; s < nst; s++) {
        if (s + 2 < nst)      cp_wait2();
        else if (s + 1 < nst) cp_wait1();
        else                  cp_wait0();
        __syncthreads();

        uint32_t st = sb + buf * STAGE_BYTES;
#pragma unroll
        for (int kb = 0; kb < BK; kb += 16) {
            const uint32_t kbo = (uint32_t)kb * 2;
            uint32_t ah[2][4], al[2][4];
            ldsm4(ah[0], st + OFF_AH + a_rb0 + kbo);
            ldsm4(al[0], st + OFF_AL + a_rb0 + kbo);
            ldsm4(ah[1], st + OFF_AH + a_rb1 + kbo);
            ldsm4(al[1], st + OFF_AL + a_rb1 + kbo);

            uint32_t bh[4][2], bl[4][2];
#pragma unroll
            for (int p = 0; p < 2; p++) {
                uint32_t ro = (p ? b_rb1 : b_rb0) + kbo;
                uint32_t r[4];
                ldsm4(r, st + OFF_BH + ro);
                bh[p*2][0] = r[0]; bh[p*2][1] = r[1];
                bh[p*2+1][0] = r[2]; bh[p*2+1][1] = r[3];
                ldsm4(r, st + OFF_BL + ro);
                bl[p*2][0] = r[0]; bl[p*2][1] = r[1];
                bl[p*2+1][0] = r[2]; bl[p*2+1][1] = r[3];
            }
#pragma unroll
            for (int mt = 0; mt < 2; mt++)
#pragma unroll
                for (int nt = 0; nt < 4; nt++) {
                    mma_f16(acc_hi[mt][nt], ah[mt], bh[nt]);   // ~1
                    mma_f16(acc_lo[mt][nt], ah[mt], bl[nt]);   // ~2^-11
                    mma_f16(acc_lo[mt][nt], al[mt], bh[nt]);   // ~2^-11
                }
        }

        // fold tensor accumulators into fp32 master every 256 K
        if ((s & 3) == 3 || s == nst - 1) {
#pragma unroll
            for (int mt = 0; mt < 2; mt++)
#pragma unroll
                for (int nt = 0; nt < 4; nt++)
#pragma unroll
                    for (int k = 0; k < 4; k++) {
                        master[mt][nt][k] += acc_hi[mt][nt][k] + acc_lo[mt][nt][k];
                        acc_hi[mt][nt][k] = 0.f;
                        acc_lo[mt][nt][k] = 0.f;
                    }
        }
        __syncthreads();
        if (s + NSTAGE < nst) {
            load_stage(buf, zb + s + NSTAGE);
            cp_commit();
        } else {
            cp_commit();
        }
        buf = (buf + 1 == NSTAGE) ? 0 : buf + 1;
    }

    // ---- epilogue: unscale, add bias (z==0 only), store fp32 partial ----
    const int er = lane >> 2;
    const int ec = (lane & 3) * 2;
    const float bmul = (blockIdx.z == 0) ? 1.f : 0.f;
    float* Cz = C + (size_t)blockIdx.z * (size_t)(gridDim.y * BM) * Nact;
#pragma unroll
    for (int mt = 0; mt < 2; mt++) {
        int row = m0 + wm * 32 + mt * 16 + er;
#pragma unroll
        for (int nt = 0; nt < 4; nt++) {
            int col = n0 + wn * 32 + nt * 8 + ec;
            float* c = master[mt][nt];
            if (col < Nact) {
                float b0 = bias[col] * bmul;
                Cz[(size_t)row * Nact + col]       = c[0] * outScale + b0;
                Cz[(size_t)(row + 8) * Nact + col] = c[2] * outScale + b0;
                if (col + 1 < Nact) {
                    float b1 = bias[col + 1] * bmul;
                    Cz[(size_t)row * Nact + col + 1]       = c[1] * outScale + b1;
                    Cz[(size_t)(row + 8) * Nact + col + 1] = c[3] * outScale + b1;
                }
            }
        }
    }
}

// ---------------- conversions ----------------------------------------------
// 2 elems/thread, half2 stores
__global__ void split_pad_kernel(const float* __restrict__ X,
                                 __half* __restrict__ Xh,
                                 __half* __restrict__ Xl,
                                 int M, int K, int Kpad)
{
    size_t i2 = (size_t)blockIdx.x * blockDim.x + threadIdx.x;
    size_t tot2 = (size_t)M * Kpad / 2;
    if (i2 >= tot2) return;
    int row = (int)(i2 / (Kpad / 2));
    int c0  = (int)(i2 % (Kpad / 2)) * 2;
    float v0 = (c0     < K) ? __ldg(X + (size_t)row * K + c0)     : 0.f;
    float v1 = (c0 + 1 < K) ? __ldg(X + (size_t)row * K + c0 + 1) : 0.f;
    __half h0, l0, h1, l1;
    split2(v0, h0, l0);
    split2(v1, h1, l1);
    __half2 hh; hh.x = h0; hh.y = h1;
    __half2 ll; ll.x = l0; ll.y = l1;
    reinterpret_cast<__half2*>(Xh)[i2] = hh;
    reinterpret_cast<__half2*>(Xl)[i2] = ll;
}

// ---------------- transpose v2: 64k x 32n tiles, half2 stores ---------------
__global__ void transpose_split_kernel(const float* __restrict__ W,
                                       __half* __restrict__ Wh,
                                       __half* __restrict__ Wl,
                                       int K, int N, int Kpad)
{
    __shared__ float t[64][33];
    int kb = blockIdx.x * 64, nb = blockIdx.y * 32;
    int tx = threadIdx.x, ty = threadIdx.y;   // block (32,8)
#pragma unroll
    for (int yy = 0; yy < 8; yy++) {
        int k = kb + ty + yy * 8, n = nb + tx;
        t[ty + yy * 8][tx] = (k < K && n < N) ? W[(size_t)k * N + n] : 0.f;
    }
    __syncthreads();
#pragma unroll
    for (int yy = 0; yy < 4; yy++) {
        int n = nb + ty + yy * 8;
        int k = kb + tx * 2;
        float v0 = t[tx * 2][ty + yy * 8] * WSCALE;
        float v1 = t[tx * 2 + 1][ty + yy * 8] * WSCALE;
        __half h0, l0, h1, l1;
        split2(v0, h0, l0);
        split2(v1, h1, l1);
        __half2 hh; hh.x = h0; hh.y = h1;
        __half2 ll; ll.x = l0; ll.y = l1;
        size_t o2 = ((size_t)n * Kpad + k) / 2;
        reinterpret_cast<__half2*>(Wh)[o2] = hh;
        reinterpret_cast<__half2*>(Wl)[o2] = ll;
    }
}

// ---------------- batchnorm (two-phase stats, float2 columns) ---------------
__global__ void bn_stats_part(const float* __restrict__ X,
                              const float* __restrict__ X2,
                              float* __restrict__ psum, float* __restrict__ psq,
                              int M, int N)
{
    int lane  = threadIdx.x & 31;
    int ry    = threadIdx.x >> 5;           // 0..7
    int col   = blockIdx.x * 64 + lane * 2; // 2 cols per thread
    int chunk = blockIdx.y;
    int rows  = M / BN_CH;
    int r0    = chunk * rows;
    float s0 = 0.f, q0 = 0.f, s1 = 0.f, q1 = 0.f;
    for (int r = r0 + ry; r < r0 + rows; r += 8) {
        size_t o2 = ((size_t)r * N + col) / 2;
        float2 a = reinterpret_cast<const float2*>(X)[o2];
        float2 b = reinterpret_cast<const float2*>(X2)[o2];
        float v0 = a.x + b.x, v1 = a.y + b.y;
        s0 += v0; q0 += v0 * v0;
        s1 += v1; q1 += v1 * v1;
    }
    __shared__ float ss[8][64], sq[8][64];
    ss[ry][lane * 2] = s0;     sq[ry][lane * 2] = q0;
    ss[ry][lane * 2 + 1] = s1; sq[ry][lane * 2 + 1] = q1;
    __syncthreads();
    if (ry < 2) {
        int c = lane + ry * 32;
        float s = 0.f, q = 0.f;
#pragma unroll
        for (int i = 0; i < 8; i++) { s += ss[i][c]; q += sq[i][c]; }
        psum[chunk * N + blockIdx.x * 64 + c] = s;
        psq [chunk * N + blockIdx.x * 64 + c] = q;
    }
}

__global__ void bn_stats_final(const float* __restrict__ psum,
                               const float* __restrict__ psq,
                               const float* __restrict__ gamma,
                               const float* __restrict__ beta,
                               float* __restrict__ scale,
                               float* __restrict__ shift,
                               int N, int M)
{
    int col = blockIdx.x * blockDim.x + threadIdx.x;
    if (col >= N) return;
    float s = 0.f, q = 0.f;
#pragma unroll
    for (int c = 0; c < BN_CH; c++) { s += psum[c * N + col]; q += psq[c * N + col]; }
    float inv = 1.f / (float)M;
    float mu  = s * inv;
    float var = q * inv - mu * mu;
    float rs  = rsqrtf(var + BN_EPS);
    float sc  = gamma[col] * rs;
    scale[col] = sc;
    shift[col] = beta[col] - mu * sc;
}

__global__ void bn_apply_split_kernel(const float* __restrict__ X,
                                      const float* __restrict__ X2,
                                      const float* __restrict__ scale,
                                      const float* __restrict__ shift,
                                      const float* __restrict__ res,
                                      float* __restrict__ Yf,
                                      __half* __restrict__ Yh,
                                      __half* __restrict__ Yl,
                                      int total4, int N)
{
    int i = blockIdx.x * blockDim.x + threadIdx.x;
    if (i >= total4) return;
    int c0 = (i * 4) & (N - 1);
    float4 x  = reinterpret_cast<const float4*>(X)[i];
    float4 x2 = reinterpret_cast<const float4*>(X2)[i];
    x.x += x2.x; x.y += x2.y; x.z += x2.z; x.w += x2.w;
    float4 o;
    o.x = x.x * scale[c0 + 0] + shift[c0 + 0];
    o.y = x.y * scale[c0 + 1] + shift[c0 + 1];
    o.z = x.z * scale[c0 + 2] + shift[c0 + 2];
    o.w = x.w * scale[c0 + 3] + shift[c0 + 3];
    if (res) {
        float4 h = reinterpret_cast<const float4*>(res)[i];
        o.x += h.x; o.y += h.y; o.z += h.z; o.w += h.w;
    }
    o.x = fmaxf(o.x, 0.f); o.y = fmaxf(o.y, 0.f);
    o.z = fmaxf(o.z, 0.f); o.w = fmaxf(o.w, 0.f);
    if (Yf) reinterpret_cast<float4*>(Yf)[i] = o;

    if (Yh) {
        float v[4] = {o.x, o.y, o.z, o.w};
        __half h4[4], l4[4];
#pragma unroll
        for (int k = 0; k < 4; k++) split2(v[k], h4[k], l4[k]);
        reinterpret_cast<uint2*>(Yh)[i] = *reinterpret_cast<uint2*>(h4);
        reinterpret_cast<uint2*>(Yl)[i] = *reinterpret_cast<uint2*>(l4);
    }
}

// ---------------- polar factor of 3x3 + tail copy ---------------------------
__global__ void polar_tail_kernel(const float* __restrict__ O,
                                  float* __restrict__ out, int B)
{
    int i = blockIdx.x * blockDim.x + threadIdx.x;
    int nmat = B * 24;
    if (i < nmat) {
        int b = i / 24, j = i % 24;
        const float* m = O + (size_t)b * OUT_DIM + j * 9;
        float X[9];
#pragma unroll
        for (int k = 0; k < 9; k++) X[k] = m[k];
#pragma unroll
        for (int it = 0; it < 14; it++) {
            float C0 = X[4]*X[8] - X[5]*X[7];
            float C1 = X[5]*X[6] - X[3]*X[8];
            float C2 = X[3]*X[7] - X[4]*X[6];
            float C3 = X[2]*X[7] - X[1]*X[8];
            float C4 = X[0]*X[8] - X[2]*X[6];
            float C5 = X[1]*X[6] - X[0]*X[7];
            float C6 = X[1]*X[5] - X[2]*X[4];
            float C7 = X[2]*X[3] - X[0]*X[5];
            float C8 = X[0]*X[4] - X[1]*X[3];
            float d  = X[0]*C0 + X[1]*C1 + X[2]*C2;
            float ad = fmaxf(fabsf(d), 1e-30f);
            float g  = 1.f / cbrtf(ad);
            float c2 = copysignf(g * g, d);
            X[0] = 0.5f*(g*X[0] + c2*C0);
            X[1] = 0.5f*(g*X[1] + c2*C1);
            X[2] = 0.5f*(g*X[2] + c2*C2);
            X[3] = 0.5f*(g*X[3] + c2*C3);
            X[4] = 0.5f*(g*X[4] + c2*C4);
            X[5] = 0.5f*(g*X[5] + c2*C5);
            X[6] = 0.5f*(g*X[6] + c2*C6);
            X[7] = 0.5f*(g*X[7] + c2*C7);
            X[8] = 0.5f*(g*X[8] + c2*C8);
        }
        float det = X[0]*(X[4]*X[8]-X[5]*X[7])
                  - X[1]*(X[3]*X[8]-X[5]*X[6])
                  + X[2]*(X[3]*X[7]-X[4]*X[6]);
        float s = (det >= 0.f) ? 1.f : -1.f;
        float* dst = out + (size_t)i * 9;
#pragma unroll
        for (int k = 0; k < 9; k++) dst[k] = X[k] * s;
    } else {
        int t13 = i - nmat;
        if (t13 >= B * 13) return;
        int b = t13 / 13, t = t13 % 13;
        size_t betas_off  = (size_t)B * 216;
        size_t camera_off = betas_off + (size_t)B * 10;
        if (t < 10)
            out[betas_off + (size_t)b * 10 + t] = O[(size_t)b * OUT_DIM + 216 + t];
        else
            out[camera_off + (size_t)b * 3 + (t - 10)] = O[(size_t)b * OUT_DIM + 226 + (t - 10)];
    }
}

// ---------------------------------------------------------------------------
static void launch_gemm_sk2(const __half* Ah, const __half* Al,
                            const __half* Bh, const __half* Bl,
                            const float* bias, float* C, int Kpad, int Npad)
{
    dim3 grid(Npad / BNT, B_BATCH / BM, 2);
    mma_gemm<<<grid, 256, SMEM_REQ>>>(Ah, Al, Bh, Bl, bias, C,
                                      Kpad, Npad, Kpad / BK / 2, INV_WSCALE);
}

static void launch_bn(const float* X, const float* X2,
                      const float* g, const float* be,
                      float* scale, float* shift, float* psum, float* psq,
                      const float* res, float* Yf, __half* Yh, __half* Yl)
{
    bn_stats_part<<<dim3(H_DIM / 64, BN_CH), 256>>>(X, X2, psum, psq, B_BATCH, H_DIM);
    bn_stats_final<<<(H_DIM + 255) / 256, 256>>>(psum, psq, g, be, scale, shift,
                                                 H_DIM, B_BATCH);
    int total4 = B_BATCH * H_DIM / 4;
    bn_apply_split_kernel<<<(total4 + 255) / 256, 256>>>(X, X2, scale, shift, res,
                                                         Yf, Yh, Yl, total4, H_DIM);
}

extern "C" void kernel_launch(void* const* d_in, const int* in_sizes, int n_in,
                              void* d_out, int out_size)
{
    const float* x    = (const float*)d_in[0];
    const float* w1   = (const float*)d_in[1];
    const float* b1   = (const float*)d_in[2];
    const float* g1   = (const float*)d_in[3];
    const float* be1  = (const float*)d_in[4];
    const float* w2a  = (const float*)d_in[5];
    const float* b2a  = (const float*)d_in[6];
    const float* g2a  = (const float*)d_in[7];
    const float* be2a = (const float*)d_in[8];
    const float* w2b  = (const float*)d_in[9];
    const float* b2b  = (const float*)d_in[10];
    const float* g2b  = (const float*)d_in[11];
    const float* be2b = (const float*)d_in[12];
    const float* w3a  = (const float*)d_in[13];
    const float* b3a  = (const float*)d_in[14];
    const float* g3a  = (const float*)d_in[15];
    const float* be3a = (const float*)d_in[16];
    const float* w3b  = (const float*)d_in[17];
    const float* b3b  = (const float*)d_in[18];
    const float* g3b  = (const float*)d_in[19];
    const float* be3b = (const float*)d_in[20];
    const float* w4   = (const float*)d_in[21];
    const float* b4   = (const float*)d_in[22];
    float* out = (float*)d_out;

    cudaFuncSetAttribute(mma_gemm, cudaFuncAttributeMaxDynamicSharedMemorySize,
                         SMEM_REQ);

    float *A, *A2, *H0, *H1, *O4, *sc, *sh, *ps, *pq;
    __half *Xh, *Xl, *AhB, *AlB;
    __half *W1h, *W1l, *W2ah, *W2al, *W2bh, *W2bl, *W3ah, *W3al, *W3bh, *W3bl;
    __half *W4h, *W4l;
    cudaGetSymbolAddress((void**)&A,  g_A);
    cudaGetSymbolAddress((void**)&A2, g_A2);
    cudaGetSymbolAddress((void**)&H0, g_H0);
    cudaGetSymbolAddress((void**)&H1, g_H1);
    cudaGetSymbolAddress((void**)&O4, g_O4);
    cudaGetSymbolAddress((void**)&sc, g_scale);
    cudaGetSymbolAddress((void**)&sh, g_shift);
    cudaGetSymbolAddress((void**)&ps, g_psum);
    cudaGetSymbolAddress((void**)&pq, g_psq);
    cudaGetSymbolAddress((void**)&Xh, g_Xh);
    cudaGetSymbolAddress((void**)&Xl, g_Xl);
    cudaGetSymbolAddress((void**)&AhB, g_Ah);
    cudaGetSymbolAddress((void**)&AlB, g_Al);
    cudaGetSymbolAddress((void**)&W1h, g_W1h);   cudaGetSymbolAddress((void**)&W1l, g_W1l);
    cudaGetSymbolAddress((void**)&W2ah, g_W2ah); cudaGetSymbolAddress((void**)&W2al, g_W2al);
    cudaGetSymbolAddress((void**)&W2bh, g_W2bh); cudaGetSymbolAddress((void**)&W2bl, g_W2bl);
    cudaGetSymbolAddress((void**)&W3ah, g_W3ah); cudaGetSymbolAddress((void**)&W3al, g_W3al);
    cudaGetSymbolAddress((void**)&W3bh, g_W3bh); cudaGetSymbolAddress((void**)&W3bl, g_W3bl);
    cudaGetSymbolAddress((void**)&W4h, g_W4h);   cudaGetSymbolAddress((void**)&W4l, g_W4l);

    // --- conversions --------------------------------------------------------
    dim3 blk(32, 8);
    {
        size_t tot2 = (size_t)B_BATCH * IN_PAD / 2;
        split_pad_kernel<<<(unsigned)((tot2 + 255) / 256), 256>>>(x, Xh, Xl,
                                                                  B_BATCH, IN_DIM, IN_PAD);
        transpose_split_kernel<<<dim3(IN_PAD / 64, H_DIM / 32), blk>>>(w1, W1h, W1l, IN_DIM, H_DIM, IN_PAD);
        transpose_split_kernel<<<dim3(H_DIM / 64, H_DIM / 32), blk>>>(w2a, W2ah, W2al, H_DIM, H_DIM, H_DIM);
        transpose_split_kernel<<<dim3(H_DIM / 64, H_DIM / 32), blk>>>(w2b, W2bh, W2bl, H_DIM, H_DIM, H_DIM);
        transpose_split_kernel<<<dim3(H_DIM / 64, H_DIM / 32), blk>>>(w3a, W3ah, W3al, H_DIM, H_DIM, H_DIM);
        transpose_split_kernel<<<dim3(H_DIM / 64, H_DIM / 32), blk>>>(w3b, W3bh, W3bl, H_DIM, H_DIM, H_DIM);
        transpose_split_kernel<<<dim3(H_DIM / 64, OUT_PAD / 32), blk>>>(w4, W4h, W4l, H_DIM, OUT_DIM, H_DIM);
    }

    // split-K=2 adjacency check (same as R11)
    float* Abase = A;
    {
        ptrdiff_t diff = A2 - A;
        if (diff == (ptrdiff_t)B_BATCH * H_DIM) {
            Abase = A;
        } else if (-diff == (ptrdiff_t)B_BATCH * H_DIM) {
            Abase = A2;
            float* t = A; A = A2; A2 = t;
        } else {
            Abase = nullptr;
        }
    }

    if (Abase) {
        // --- layer 1 ---
        launch_gemm_sk2(Xh, Xl, W1h, W1l, b1, Abase, IN_PAD, H_DIM);
        launch_bn(A, A2, g1, be1, sc, sh, ps, pq, nullptr, H0, AhB, AlB);
        // --- resblock 2 ---
        launch_gemm_sk2(AhB, AlB, W2ah, W2al, b2a, Abase, H_DIM, H_DIM);
        launch_bn(A, A2, g2a, be2a, sc, sh, ps, pq, nullptr, nullptr, AhB, AlB);
        launch_gemm_sk2(AhB, AlB, W2bh, W2bl, b2b, Abase, H_DIM, H_DIM);
        launch_bn(A, A2, g2b, be2b, sc, sh, ps, pq, H0, H1, AhB, AlB);
        // --- resblock 3 ---
        launch_gemm_sk2(AhB, AlB, W3ah, W3al, b3a, Abase, H_DIM, H_DIM);
        launch_bn(A, A2, g3a, be3a, sc, sh, ps, pq, nullptr, nullptr, AhB, AlB);
        launch_gemm_sk2(AhB, AlB, W3bh, W3bl, b3b, Abase, H_DIM, H_DIM);
        launch_bn(A, A2, g3b, be3b, sc, sh, ps, pq, H1, nullptr, AhB, AlB);
    } else {
        // fallback: unsplit (z=1); X2 = zeroed H1
        cudaMemsetAsync(H1, 0, (size_t)B_BATCH * H_DIM * sizeof(float));
        dim3 grid(H_DIM / BNT, B_BATCH / BM, 1);
        mma_gemm<<<grid, 256, SMEM_REQ>>>(Xh, Xl, W1h, W1l, b1, A,
                                          IN_PAD, H_DIM, IN_PAD / BK, INV_WSCALE);
        launch_bn(A, H1, g1, be1, sc, sh, ps, pq, nullptr, H0, AhB, AlB);
        mma_gemm<<<grid, 256, SMEM_REQ>>>(AhB, AlB, W2ah, W2al, b2a, A,
                                          H_DIM, H_DIM, H_DIM / BK, INV_WSCALE);
        launch_bn(A, H1, g2a, be2a, sc, sh, ps, pq, nullptr, nullptr, AhB, AlB);
        mma_gemm<<<grid, 256, SMEM_REQ>>>(AhB, AlB, W2bh, W2bl, b2b, A,
                                          H_DIM, H_DIM, H_DIM / BK, INV_WSCALE);
        launch_bn(A, H1, g2b, be2b, sc, sh, ps, pq, H0, H0, AhB, AlB);
        mma_gemm<<<grid, 256, SMEM_REQ>>>(AhB, AlB, W3ah, W3al, b3a, A,
                                          H_DIM, H_DIM, H_DIM / BK, INV_WSCALE);
        launch_bn(A, H1, g3a, be3a, sc, sh, ps, pq, nullptr, nullptr, AhB, AlB);
        mma_gemm<<<grid, 256, SMEM_REQ>>>(AhB, AlB, W3bh, W3bl, b3b, A,
                                          H_DIM, H_DIM, H_DIM / BK, INV_WSCALE);
        launch_bn(A, H1, g3b, be3b, sc, sh, ps, pq, H0, nullptr, AhB, AlB);
    }

    // --- output head via mma (single wave, no split) ------------------------
    {
        dim3 grid(OUT_PAD / BNT, B_BATCH / BM, 1);
        mma_gemm<<<grid, 256, SMEM_REQ>>>(AhB, AlB, W4h, W4l, b4, O4,
                                          H_DIM, OUT_DIM, H_DIM / BK, INV_WSCALE);
    }

    // --- polar + tail (merged) ----------------------------------------------
    int ntot = B_BATCH * 24 + B_BATCH * 13;
    polar_tail_kernel<<<(ntot + 127) / 128, 128>>>(O4, out, B_BATCH);
}

// round 17
// speedup vs baseline: 1.0169x; 1.0169x over previous
#include <cuda_runtime.h>
#include <cuda_fp16.h>
#include <math.h>
#include <stdint.h>

#define B_BATCH 4096
#define H_DIM   1024
#define IN_DIM  10338
#define IN_PAD  10496                       // 41 * 256 (divisible by 2*BK)
#define OUT_DIM 229
#define OUT_PAD 256
#define BN_EPS  1e-5f
#define WSCALE    512.0f
#define INV_WSCALE (1.0f / 512.0f)

// ---------------- MMA GEMM tiling -------------------------------------------
#define BM 128
#define BNT 64
#define BK 128
#define SMS 136                             // smem row stride in fp16 (272B)
#define A_CB (BM * SMS * 2)                 // 34816 bytes per class
#define B_CB (BNT * SMS * 2)                // 17408 bytes per class
#define OFF_AH 0
#define OFF_AL (A_CB)
#define OFF_BH (2 * A_CB)
#define OFF_BL (2 * A_CB + B_CB)
#define STAGE_BYTES (2 * A_CB + 2 * B_CB)   // 104448
#define NSTAGE 2
#define SMEM_REQ (NSTAGE * STAGE_BYTES)     // 208896

#define BN_CH 16                            // bn stats row chunks

// ---------------- scratch (device globals; no allocation allowed) ----------
__device__ float g_A [(size_t)B_BATCH * H_DIM];   // split-K partial z=0
__device__ float g_A2[(size_t)B_BATCH * H_DIM];   // split-K partial z=1
__device__ float g_H0[(size_t)B_BATCH * H_DIM];
__device__ float g_H1[(size_t)B_BATCH * H_DIM];
__device__ float g_O4[(size_t)B_BATCH * OUT_DIM];
__device__ float g_scale[H_DIM];
__device__ float g_shift[H_DIM];
__device__ float g_psum[BN_CH * H_DIM];
__device__ float g_psq [BN_CH * H_DIM];

__device__ __half g_Xh[(size_t)B_BATCH * IN_PAD];
__device__ __half g_Xl[(size_t)B_BATCH * IN_PAD];
__device__ __half g_Ah[(size_t)B_BATCH * H_DIM];
__device__ __half g_Al[(size_t)B_BATCH * H_DIM];

__device__ __half g_W1h[(size_t)H_DIM * IN_PAD];
__device__ __half g_W1l[(size_t)H_DIM * IN_PAD];
__device__ __half g_W2ah[(size_t)H_DIM * H_DIM];
__device__ __half g_W2al[(size_t)H_DIM * H_DIM];
__device__ __half g_W2bh[(size_t)H_DIM * H_DIM];
__device__ __half g_W2bl[(size_t)H_DIM * H_DIM];
__device__ __half g_W3ah[(size_t)H_DIM * H_DIM];
__device__ __half g_W3al[(size_t)H_DIM * H_DIM];
__device__ __half g_W3bh[(size_t)H_DIM * H_DIM];
__device__ __half g_W3bl[(size_t)H_DIM * H_DIM];
__device__ __half g_W4h[(size_t)OUT_PAD * H_DIM];
__device__ __half g_W4l[(size_t)OUT_PAD * H_DIM];

// ---------------- PTX helpers (baseline PTX; no sm_103a features) ----------
__device__ __forceinline__ uint32_t smem_u32(const void* p) {
    uint32_t a;
    asm("{ .reg .u64 t; cvta.to.shared.u64 t, %1; cvt.u32.u64 %0, t; }"
        : "=r"(a) : "l"(p));
    return a;
}
__device__ __forceinline__ void cp16(uint32_t dst, const void* src) {
    asm volatile("cp.async.cg.shared.global [%0], [%1], 16;" :: "r"(dst), "l"(src));
}
__device__ __forceinline__ void cp_commit() { asm volatile("cp.async.commit_group;" ::: "memory"); }
__device__ __forceinline__ void cp_wait1()  { asm volatile("cp.async.wait_group 1;" ::: "memory"); }
__device__ __forceinline__ void cp_wait0()  { asm volatile("cp.async.wait_group 0;" ::: "memory"); }

__device__ __forceinline__ void ldsm4(uint32_t r[4], uint32_t addr) {
    asm volatile("ldmatrix.sync.aligned.m8n8.x4.shared.b16 {%0,%1,%2,%3}, [%4];"
                 : "=r"(r[0]), "=r"(r[1]), "=r"(r[2]), "=r"(r[3]) : "r"(addr));
}
__device__ __forceinline__ void mma_f16(float c[4], const uint32_t a[4],
                                        const uint32_t b[2]) {
    asm volatile(
        "mma.sync.aligned.m16n8k16.row.col.f32.f16.f16.f32 "
        "{%0,%1,%2,%3}, {%4,%5,%6,%7}, {%8,%9}, {%0,%1,%2,%3};"
        : "+f"(c[0]), "+f"(c[1]), "+f"(c[2]), "+f"(c[3])
        : "r"(a[0]), "r"(a[1]), "r"(a[2]), "r"(a[3]), "r"(b[0]), "r"(b[1]));
}

// 2-way fp16 split: v = h + l + e, |e| <= 2^-23 |v| (for normal-range l)
__device__ __forceinline__ void split2(float v, __half& h, __half& l) {
    h = __float2half_rn(v);
    l = __float2half_rn(v - __half2float(h));
}

// ---------------- GEMM (fp16 2-split, 3-term, dual acc + fp32 master) ------
// Split-K along blockIdx.z: z-slice covers K chunks [z*nst, (z+1)*nst).
// Partial output z goes to C + z*M*Nact; bias added only by z==0.
__global__ void __launch_bounds__(256, 1)
mma_gemm(const __half* __restrict__ Ah, const __half* __restrict__ Al,
         const __half* __restrict__ Bh, const __half* __restrict__ Bl,
         const float* __restrict__ bias, float* __restrict__ C,
         int Kpad, int Nact, int nst, float outScale)
{
    extern __shared__ char smem[];
    const int tid  = threadIdx.x;
    const int wid  = tid >> 5;
    const int lane = tid & 31;
    const int m0   = blockIdx.y * BM;
    const int n0   = blockIdx.x * BNT;
    const int zb   = blockIdx.z * nst;
    const uint32_t sb = smem_u32(smem);

    const int wm = wid & 3;
    const int wn = wid >> 2;

    float acc_hi[2][4][4], acc_lo[2][4][4], master[2][4][4];
#pragma unroll
    for (int i = 0; i < 2; i++)
#pragma unroll
        for (int j = 0; j < 4; j++)
#pragma unroll
            for (int k = 0; k < 4; k++) {
                acc_hi[i][j][k] = 0.f; acc_lo[i][j][k] = 0.f; master[i][j][k] = 0.f;
            }

    const int a_row  = lane & 15;
    const int a_koff = (lane >> 4) << 3;
    const int b_nr   = (lane & 7) + ((lane >> 4) << 3);
    const int b_koff = ((lane >> 3) & 1) << 3;

    const uint32_t a_rb0 = (uint32_t)(wm * 32 + a_row) * (SMS * 2) + a_koff * 2;
    const uint32_t a_rb1 = a_rb0 + 16 * (SMS * 2);
    const uint32_t b_rb0 = (uint32_t)(wn * 32 + b_nr) * (SMS * 2) + b_koff * 2;
    const uint32_t b_rb1 = b_rb0 + 16 * (SMS * 2);

    auto load_stage = [&](int s, int chunk) {
        uint32_t st = sb + s * STAGE_BYTES;
        int k0 = chunk * BK;
#pragma unroll
        for (int i = 0; i < 8; i++) {                 // A: 128 rows x 16 granules
            int g = tid + i * 256;
            int row = g >> 4, gc = g & 15;
            size_t  go = (size_t)(m0 + row) * Kpad + k0 + gc * 8;
            uint32_t so = row * (SMS * 2) + gc * 16;
            cp16(st + OFF_AH + so, Ah + go);
            cp16(st + OFF_AL + so, Al + go);
        }
#pragma unroll
        for (int i = 0; i < 4; i++) {                 // B: 64 rows x 16 granules
            int g = tid + i * 256;
            int row = g >> 4, gc = g & 15;
            size_t  go = (size_t)(n0 + row) * Kpad + k0 + gc * 8;
            uint32_t so = row * (SMS * 2) + gc * 16;
            cp16(st + OFF_BH + so, Bh + go);
            cp16(st + OFF_BL + so, Bl + go);
        }
    };

    // prologue: fill 2 stages
#pragma unroll
    for (int i = 0; i < NSTAGE; i++) {
        if (i < nst) load_stage(i, zb + i);
        cp_commit();
    }

    int buf = 0;
    for (int s = 0; s < nst; s++) {
        if (s + 1 < nst) cp_wait1(); else cp_wait0();
        __syncthreads();

        uint32_t st = sb + buf * STAGE_BYTES;
#pragma unroll
        for (int kb = 0; kb < BK; kb += 16) {
            const uint32_t kbo = (uint32_t)kb * 2;
            uint32_t ah[2][4], al[2][4];
            ldsm4(ah[0], st + OFF_AH + a_rb0 + kbo);
            ldsm4(al[0], st + OFF_AL + a_rb0 + kbo);
            ldsm4(ah[1], st + OFF_AH + a_rb1 + kbo);
            ldsm4(al[1], st + OFF_AL + a_rb1 + kbo);

            uint32_t bh[4][2], bl[4][2];
#pragma unroll
            for (int p = 0; p < 2; p++) {
                uint32_t ro = (p ? b_rb1 : b_rb0) + kbo;
                uint32_t r[4];
                ldsm4(r, st + OFF_BH + ro);
                bh[p*2][0] = r[0]; bh[p*2][1] = r[1];
                bh[p*2+1][0] = r[2]; bh[p*2+1][1] = r[3];
                ldsm4(r, st + OFF_BL + ro);
                bl[p*2][0] = r[0]; bl[p*2][1] = r[1];
                bl[p*2+1][0] = r[2]; bl[p*2+1][1] = r[3];
            }
#pragma unroll
            for (int mt = 0; mt < 2; mt++)
#pragma unroll
                for (int nt = 0; nt < 4; nt++) {
                    mma_f16(acc_hi[mt][nt], ah[mt], bh[nt]);   // ~1
                    mma_f16(acc_lo[mt][nt], ah[mt], bl[nt]);   // ~2^-11
                    mma_f16(acc_lo[mt][nt], al[mt], bh[nt]);   // ~2^-11
                }
        }

        // fold tensor accumulators into fp32 master every 256 K
        if ((s & 1) == 1 || s == nst - 1) {
#pragma unroll
            for (int mt = 0; mt < 2; mt++)
#pragma unroll
                for (int nt = 0; nt < 4; nt++)
#pragma unroll
                    for (int k = 0; k < 4; k++) {
                        master[mt][nt][k] += acc_hi[mt][nt][k] + acc_lo[mt][nt][k];
                        acc_hi[mt][nt][k] = 0.f;
                        acc_lo[mt][nt][k] = 0.f;
                    }
        }
        __syncthreads();
        if (s + NSTAGE < nst) {
            load_stage(buf, zb + s + NSTAGE);
            cp_commit();
        } else {
            cp_commit();
        }
        buf ^= 1;
    }

    // ---- epilogue: unscale, add bias (z==0 only), store fp32 partial ----
    const int er = lane >> 2;
    const int ec = (lane & 3) * 2;
    const float bmul = (blockIdx.z == 0) ? 1.f : 0.f;
    float* Cz = C + (size_t)blockIdx.z * (size_t)(gridDim.y * BM) * Nact;
#pragma unroll
    for (int mt = 0; mt < 2; mt++) {
        int row = m0 + wm * 32 + mt * 16 + er;
#pragma unroll
        for (int nt = 0; nt < 4; nt++) {
            int col = n0 + wn * 32 + nt * 8 + ec;
            float* c = master[mt][nt];
            if (col < Nact) {
                float b0 = bias[col] * bmul;
                Cz[(size_t)row * Nact + col]       = c[0] * outScale + b0;
                Cz[(size_t)(row + 8) * Nact + col] = c[2] * outScale + b0;
                if (col + 1 < Nact) {
                    float b1 = bias[col + 1] * bmul;
                    Cz[(size_t)row * Nact + col + 1]       = c[1] * outScale + b1;
                    Cz[(size_t)(row + 8) * Nact + col + 1] = c[3] * outScale + b1;
                }
            }
        }
    }
}

// ---------------- conversions ----------------------------------------------
// 2 elems/thread, half2 stores
__global__ void split_pad_kernel(const float* __restrict__ X,
                                 __half* __restrict__ Xh,
                                 __half* __restrict__ Xl,
                                 int M, int K, int Kpad)
{
    size_t i2 = (size_t)blockIdx.x * blockDim.x + threadIdx.x;
    size_t tot2 = (size_t)M * Kpad / 2;
    if (i2 >= tot2) return;
    int row = (int)(i2 / (Kpad / 2));
    int c0  = (int)(i2 % (Kpad / 2)) * 2;
    float v0 = (c0     < K) ? __ldg(X + (size_t)row * K + c0)     : 0.f;
    float v1 = (c0 + 1 < K) ? __ldg(X + (size_t)row * K + c0 + 1) : 0.f;
    __half h0, l0, h1, l1;
    split2(v0, h0, l0);
    split2(v1, h1, l1);
    __half2 hh; hh.x = h0; hh.y = h1;
    __half2 ll; ll.x = l0; ll.y = l1;
    reinterpret_cast<__half2*>(Xh)[i2] = hh;
    reinterpret_cast<__half2*>(Xl)[i2] = ll;
}

// ---------------- transpose v2: 64k x 32n tiles, half2 stores ---------------
__global__ void transpose_split_kernel(const float* __restrict__ W,
                                       __half* __restrict__ Wh,
                                       __half* __restrict__ Wl,
                                       int K, int N, int Kpad)
{
    __shared__ float t[64][33];
    int kb = blockIdx.x * 64, nb = blockIdx.y * 32;
    int tx = threadIdx.x, ty = threadIdx.y;   // block (32,8)
#pragma unroll
    for (int yy = 0; yy < 8; yy++) {
        int k = kb + ty + yy * 8, n = nb + tx;
        t[ty + yy * 8][tx] = (k < K && n < N) ? W[(size_t)k * N + n] : 0.f;
    }
    __syncthreads();
#pragma unroll
    for (int yy = 0; yy < 4; yy++) {
        int n = nb + ty + yy * 8;
        int k = kb + tx * 2;
        float v0 = t[tx * 2][ty + yy * 8] * WSCALE;
        float v1 = t[tx * 2 + 1][ty + yy * 8] * WSCALE;
        __half h0, l0, h1, l1;
        split2(v0, h0, l0);
        split2(v1, h1, l1);
        __half2 hh; hh.x = h0; hh.y = h1;
        __half2 ll; ll.x = l0; ll.y = l1;
        size_t o2 = ((size_t)n * Kpad + k) / 2;
        reinterpret_cast<__half2*>(Wh)[o2] = hh;
        reinterpret_cast<__half2*>(Wl)[o2] = ll;
    }
}

// ---------------- batchnorm (two-phase stats, float2 columns) ---------------
__global__ void bn_stats_part(const float* __restrict__ X,
                              const float* __restrict__ X2,
                              float* __restrict__ psum, float* __restrict__ psq,
                              int M, int N)
{
    int lane  = threadIdx.x & 31;
    int ry    = threadIdx.x >> 5;           // 0..7
    int col   = blockIdx.x * 64 + lane * 2; // 2 cols per thread
    int chunk = blockIdx.y;
    int rows  = M / BN_CH;
    int r0    = chunk * rows;
    float s0 = 0.f, q0 = 0.f, s1 = 0.f, q1 = 0.f;
    for (int r = r0 + ry; r < r0 + rows; r += 8) {
        size_t o2 = ((size_t)r * N + col) / 2;
        float2 a = reinterpret_cast<const float2*>(X)[o2];
        float2 b = reinterpret_cast<const float2*>(X2)[o2];
        float v0 = a.x + b.x, v1 = a.y + b.y;
        s0 += v0; q0 += v0 * v0;
        s1 += v1; q1 += v1 * v1;
    }
    __shared__ float ss[8][64], sq[8][64];
    ss[ry][lane * 2] = s0;     sq[ry][lane * 2] = q0;
    ss[ry][lane * 2 + 1] = s1; sq[ry][lane * 2 + 1] = q1;
    __syncthreads();
    if (ry < 2) {
        int c = lane + ry * 32;
        float s = 0.f, q = 0.f;
#pragma unroll
        for (int i = 0; i < 8; i++) { s += ss[i][c]; q += sq[i][c]; }
        psum[chunk * N + blockIdx.x * 64 + c] = s;
        psq [chunk * N + blockIdx.x * 64 + c] = q;
    }
}

__global__ void bn_stats_final(const float* __restrict__ psum,
                               const float* __restrict__ psq,
                               const float* __restrict__ gamma,
                               const float* __restrict__ beta,
                               float* __restrict__ scale,
                               float* __restrict__ shift,
                               int N, int M)
{
    int col = blockIdx.x * blockDim.x + threadIdx.x;
    if (col >= N) return;
    float s = 0.f, q = 0.f;
#pragma unroll
    for (int c = 0; c < BN_CH; c++) { s += psum[c * N + col]; q += psq[c * N + col]; }
    float inv = 1.f / (float)M;
    float mu  = s * inv;
    float var = q * inv - mu * mu;
    float rs  = rsqrtf(var + BN_EPS);
    float sc  = gamma[col] * rs;
    scale[col] = sc;
    shift[col] = beta[col] - mu * sc;
}

__global__ void bn_apply_split_kernel(const float* __restrict__ X,
                                      const float* __restrict__ X2,
                                      const float* __restrict__ scale,
                                      const float* __restrict__ shift,
                                      const float* __restrict__ res,
                                      float* __restrict__ Yf,
                                      __half* __restrict__ Yh,
                                      __half* __restrict__ Yl,
                                      int total4, int N)
{
    int i = blockIdx.x * blockDim.x + threadIdx.x;
    if (i >= total4) return;
    int c0 = (i * 4) & (N - 1);
    float4 x  = reinterpret_cast<const float4*>(X)[i];
    float4 x2 = reinterpret_cast<const float4*>(X2)[i];
    x.x += x2.x; x.y += x2.y; x.z += x2.z; x.w += x2.w;
    float4 o;
    o.x = x.x * scale[c0 + 0] + shift[c0 + 0];
    o.y = x.y * scale[c0 + 1] + shift[c0 + 1];
    o.z = x.z * scale[c0 + 2] + shift[c0 + 2];
    o.w = x.w * scale[c0 + 3] + shift[c0 + 3];
    if (res) {
        float4 h = reinterpret_cast<const float4*>(res)[i];
        o.x += h.x; o.y += h.y; o.z += h.z; o.w += h.w;
    }
    o.x = fmaxf(o.x, 0.f); o.y = fmaxf(o.y, 0.f);
    o.z = fmaxf(o.z, 0.f); o.w = fmaxf(o.w, 0.f);
    if (Yf) reinterpret_cast<float4*>(Yf)[i] = o;

    if (Yh) {
        float v[4] = {o.x, o.y, o.z, o.w};
        __half h4[4], l4[4];
#pragma unroll
        for (int k = 0; k < 4; k++) split2(v[k], h4[k], l4[k]);
        reinterpret_cast<uint2*>(Yh)[i] = *reinterpret_cast<uint2*>(h4);
        reinterpret_cast<uint2*>(Yl)[i] = *reinterpret_cast<uint2*>(l4);
    }
}

// ---------------- polar factor of 3x3 + tail copy ---------------------------
__global__ void polar_tail_kernel(const float* __restrict__ O,
                                  float* __restrict__ out, int B)
{
    int i = blockIdx.x * blockDim.x + threadIdx.x;
    int nmat = B * 24;
    if (i < nmat) {
        int b = i / 24, j = i % 24;
        const float* m = O + (size_t)b * OUT_DIM + j * 9;
        float X[9];
#pragma unroll
        for (int k = 0; k < 9; k++) X[k] = m[k];
#pragma unroll
        for (int it = 0; it < 14; it++) {
            float C0 = X[4]*X[8] - X[5]*X[7];
            float C1 = X[5]*X[6] - X[3]*X[8];
            float C2 = X[3]*X[7] - X[4]*X[6];
            float C3 = X[2]*X[7] - X[1]*X[8];
            float C4 = X[0]*X[8] - X[2]*X[6];
            float C5 = X[1]*X[6] - X[0]*X[7];
            float C6 = X[1]*X[5] - X[2]*X[4];
            float C7 = X[2]*X[3] - X[0]*X[5];
            float C8 = X[0]*X[4] - X[1]*X[3];
            float d  = X[0]*C0 + X[1]*C1 + X[2]*C2;
            float ad = fmaxf(fabsf(d), 1e-30f);
            float g  = 1.f / cbrtf(ad);
            float c2 = copysignf(g * g, d);
            X[0] = 0.5f*(g*X[0] + c2*C0);
            X[1] = 0.5f*(g*X[1] + c2*C1);
            X[2] = 0.5f*(g*X[2] + c2*C2);
            X[3] = 0.5f*(g*X[3] + c2*C3);
            X[4] = 0.5f*(g*X[4] + c2*C4);
            X[5] = 0.5f*(g*X[5] + c2*C5);
            X[6] = 0.5f*(g*X[6] + c2*C6);
            X[7] = 0.5f*(g*X[7] + c2*C7);
            X[8] = 0.5f*(g*X[8] + c2*C8);
        }
        float det = X[0]*(X[4]*X[8]-X[5]*X[7])
                  - X[1]*(X[3]*X[8]-X[5]*X[6])
                  + X[2]*(X[3]*X[7]-X[4]*X[6]);
        float s = (det >= 0.f) ? 1.f : -1.f;
        float* dst = out + (size_t)i * 9;
#pragma unroll
        for (int k = 0; k < 9; k++) dst[k] = X[k] * s;
    } else {
        int t13 = i - nmat;
        if (t13 >= B * 13) return;
        int b = t13 / 13, t = t13 % 13;
        size_t betas_off  = (size_t)B * 216;
        size_t camera_off = betas_off + (size_t)B * 10;
        if (t < 10)
            out[betas_off + (size_t)b * 10 + t] = O[(size_t)b * OUT_DIM + 216 + t];
        else
            out[camera_off + (size_t)b * 3 + (t - 10)] = O[(size_t)b * OUT_DIM + 226 + (t - 10)];
    }
}

// ---------------------------------------------------------------------------
static void launch_gemm_sk2(const __half* Ah, const __half* Al,
                            const __half* Bh, const __half* Bl,
                            const float* bias, float* C, int Kpad, int Npad)
{
    dim3 grid(Npad / BNT, B_BATCH / BM, 2);
    mma_gemm<<<grid, 256, SMEM_REQ>>>(Ah, Al, Bh, Bl, bias, C,
                                      Kpad, Npad, Kpad / BK / 2, INV_WSCALE);
}

static void launch_bn(const float* X, const float* X2,
                      const float* g, const float* be,
                      float* scale, float* shift, float* psum, float* psq,
                      const float* res, float* Yf, __half* Yh, __half* Yl)
{
    bn_stats_part<<<dim3(H_DIM / 64, BN_CH), 256>>>(X, X2, psum, psq, B_BATCH, H_DIM);
    bn_stats_final<<<(H_DIM + 255) / 256, 256>>>(psum, psq, g, be, scale, shift,
                                                 H_DIM, B_BATCH);
    int total4 = B_BATCH * H_DIM / 4;
    bn_apply_split_kernel<<<(total4 + 255) / 256, 256>>>(X, X2, scale, shift, res,
                                                         Yf, Yh, Yl, total4, H_DIM);
}

extern "C" void kernel_launch(void* const* d_in, const int* in_sizes, int n_in,
                              void* d_out, int out_size)
{
    const float* x    = (const float*)d_in[0];
    const float* w1   = (const float*)d_in[1];
    const float* b1   = (const float*)d_in[2];
    const float* g1   = (const float*)d_in[3];
    const float* be1  = (const float*)d_in[4];
    const float* w2a  = (const float*)d_in[5];
    const float* b2a  = (const float*)d_in[6];
    const float* g2a  = (const float*)d_in[7];
    const float* be2a = (const float*)d_in[8];
    const float* w2b  = (const float*)d_in[9];
    const float* b2b  = (const float*)d_in[10];
    const float* g2b  = (const float*)d_in[11];
    const float* be2b = (const float*)d_in[12];
    const float* w3a  = (const float*)d_in[13];
    const float* b3a  = (const float*)d_in[14];
    const float* g3a  = (const float*)d_in[15];
    const float* be3a = (const float*)d_in[16];
    const float* w3b  = (const float*)d_in[17];
    const float* b3b  = (const float*)d_in[18];
    const float* g3b  = (const float*)d_in[19];
    const float* be3b = (const float*)d_in[20];
    const float* w4   = (const float*)d_in[21];
    const float* b4   = (const float*)d_in[22];
    float* out = (float*)d_out;

    cudaFuncSetAttribute(mma_gemm, cudaFuncAttributeMaxDynamicSharedMemorySize,
                         SMEM_REQ);

    float *A, *A2, *H0, *H1, *O4, *sc, *sh, *ps, *pq;
    __half *Xh, *Xl, *AhB, *AlB;
    __half *W1h, *W1l, *W2ah, *W2al, *W2bh, *W2bl, *W3ah, *W3al, *W3bh, *W3bl;
    __half *W4h, *W4l;
    cudaGetSymbolAddress((void**)&A,  g_A);
    cudaGetSymbolAddress((void**)&A2, g_A2);
    cudaGetSymbolAddress((void**)&H0, g_H0);
    cudaGetSymbolAddress((void**)&H1, g_H1);
    cudaGetSymbolAddress((void**)&O4, g_O4);
    cudaGetSymbolAddress((void**)&sc, g_scale);
    cudaGetSymbolAddress((void**)&sh, g_shift);
    cudaGetSymbolAddress((void**)&ps, g_psum);
    cudaGetSymbolAddress((void**)&pq, g_psq);
    cudaGetSymbolAddress((void**)&Xh, g_Xh);
    cudaGetSymbolAddress((void**)&Xl, g_Xl);
    cudaGetSymbolAddress((void**)&AhB, g_Ah);
    cudaGetSymbolAddress((void**)&AlB, g_Al);
    cudaGetSymbolAddress((void**)&W1h, g_W1h);   cudaGetSymbolAddress((void**)&W1l, g_W1l);
    cudaGetSymbolAddress((void**)&W2ah, g_W2ah); cudaGetSymbolAddress((void**)&W2al, g_W2al);
    cudaGetSymbolAddress((void**)&W2bh, g_W2bh); cudaGetSymbolAddress((void**)&W2bl, g_W2bl);
    cudaGetSymbolAddress((void**)&W3ah, g_W3ah); cudaGetSymbolAddress((void**)&W3al, g_W3al);
    cudaGetSymbolAddress((void**)&W3bh, g_W3bh); cudaGetSymbolAddress((void**)&W3bl, g_W3bl);
    cudaGetSymbolAddress((void**)&W4h, g_W4h);   cudaGetSymbolAddress((void**)&W4l, g_W4l);

    // --- conversions --------------------------------------------------------
    dim3 blk(32, 8);
    {
        size_t tot2 = (size_t)B_BATCH * IN_PAD / 2;
        split_pad_kernel<<<(unsigned)((tot2 + 255) / 256), 256>>>(x, Xh, Xl,
                                                                  B_BATCH, IN_DIM, IN_PAD);
        transpose_split_kernel<<<dim3(IN_PAD / 64, H_DIM / 32), blk>>>(w1, W1h, W1l, IN_DIM, H_DIM, IN_PAD);
        transpose_split_kernel<<<dim3(H_DIM / 64, H_DIM / 32), blk>>>(w2a, W2ah, W2al, H_DIM, H_DIM, H_DIM);
        transpose_split_kernel<<<dim3(H_DIM / 64, H_DIM / 32), blk>>>(w2b, W2bh, W2bl, H_DIM, H_DIM, H_DIM);
        transpose_split_kernel<<<dim3(H_DIM / 64, H_DIM / 32), blk>>>(w3a, W3ah, W3al, H_DIM, H_DIM, H_DIM);
        transpose_split_kernel<<<dim3(H_DIM / 64, H_DIM / 32), blk>>>(w3b, W3bh, W3bl, H_DIM, H_DIM, H_DIM);
        transpose_split_kernel<<<dim3(H_DIM / 64, OUT_PAD / 32), blk>>>(w4, W4h, W4l, H_DIM, OUT_DIM, H_DIM);
    }

    // split-K=2 adjacency check (same as R11)
    float* Abase = A;
    {
        ptrdiff_t diff = A2 - A;
        if (diff == (ptrdiff_t)B_BATCH * H_DIM) {
            Abase = A;
        } else if (-diff == (ptrdiff_t)B_BATCH * H_DIM) {
            Abase = A2;
            float* t = A; A = A2; A2 = t;
        } else {
            Abase = nullptr;
        }
    }

    if (Abase) {
        // --- layer 1 ---
        launch_gemm_sk2(Xh, Xl, W1h, W1l, b1, Abase, IN_PAD, H_DIM);
        launch_bn(A, A2, g1, be1, sc, sh, ps, pq, nullptr, H0, AhB, AlB);
        // --- resblock 2 ---
        launch_gemm_sk2(AhB, AlB, W2ah, W2al, b2a, Abase, H_DIM, H_DIM);
        launch_bn(A, A2, g2a, be2a, sc, sh, ps, pq, nullptr, nullptr, AhB, AlB);
        launch_gemm_sk2(AhB, AlB, W2bh, W2bl, b2b, Abase, H_DIM, H_DIM);
        launch_bn(A, A2, g2b, be2b, sc, sh, ps, pq, H0, H1, AhB, AlB);
        // --- resblock 3 ---
        launch_gemm_sk2(AhB, AlB, W3ah, W3al, b3a, Abase, H_DIM, H_DIM);
        launch_bn(A, A2, g3a, be3a, sc, sh, ps, pq, nullptr, nullptr, AhB, AlB);
        launch_gemm_sk2(AhB, AlB, W3bh, W3bl, b3b, Abase, H_DIM, H_DIM);
        launch_bn(A, A2, g3b, be3b, sc, sh, ps, pq, H1, nullptr, AhB, AlB);
    } else {
        // fallback: unsplit (z=1); X2 = zeroed H1
        cudaMemsetAsync(H1, 0, (size_t)B_BATCH * H_DIM * sizeof(float));
        dim3 grid(H_DIM / BNT, B_BATCH / BM, 1);
        mma_gemm<<<grid, 256, SMEM_REQ>>>(Xh, Xl, W1h, W1l, b1, A,
                                          IN_PAD, H_DIM, IN_PAD / BK, INV_WSCALE);
        launch_bn(A, H1, g1, be1, sc, sh, ps, pq, nullptr, H0, AhB, AlB);
        mma_gemm<<<grid, 256, SMEM_REQ>>>(AhB, AlB, W2ah, W2al, b2a, A,
                                          H_DIM, H_DIM, H_DIM / BK, INV_WSCALE);
        launch_bn(A, H1, g2a, be2a, sc, sh, ps, pq, nullptr, nullptr, AhB, AlB);
        mma_gemm<<<grid, 256, SMEM_REQ>>>(AhB, AlB, W2bh, W2bl, b2b, A,
                                          H_DIM, H_DIM, H_DIM / BK, INV_WSCALE);
        launch_bn(A, H1, g2b, be2b, sc, sh, ps, pq, H0, H0, AhB, AlB);
        mma_gemm<<<grid, 256, SMEM_REQ>>>(AhB, AlB, W3ah, W3al, b3a, A,
                                          H_DIM, H_DIM, H_DIM / BK, INV_WSCALE);
        launch_bn(A, H1, g3a, be3a, sc, sh, ps, pq, nullptr, nullptr, AhB, AlB);
        mma_gemm<<<grid, 256, SMEM_REQ>>>(AhB, AlB, W3bh, W3bl, b3b, A,
                                          H_DIM, H_DIM, H_DIM / BK, INV_WSCALE);
        launch_bn(A, H1, g3b, be3b, sc, sh, ps, pq, H0, nullptr, AhB, AlB);
    }

    // --- output head via mma (single wave, no split) ------------------------
    {
        dim3 grid(OUT_PAD / BNT, B_BATCH / BM, 1);
        mma_gemm<<<grid, 256, SMEM_REQ>>>(AhB, AlB, W4h, W4l, b4, O4,
                                          H_DIM, OUT_DIM, H_DIM / BK, INV_WSCALE);
    }

    // --- polar + tail (merged) ----------------------------------------------
    int ntot = B_BATCH * 24 + B_BATCH * 13;
    polar_tail_kernel<<<(ntot + 127) / 128, 128>>>(O4, out, B_BATCH);
}